// round 15
// baseline (speedup 1.0000x reference)
#include <cuda_runtime.h>
#include <cuda_bf16.h>
#include <cstdint>

// Problem constants
#define BATCH 32
#define C     192
#define HW    3136            // 56*56
#define CHW   602112          // C*HW
#define KTOT  100352          // BATCH*HW
#define T_STEPS 96
#define NSLICE 49             // K-slices of 2048 (49*2048 = 100352)
#define KSLICE 2048
#define KCHUNK 64             // k per smem chunk (4 x k16)
#define NCHUNK 32             // KSLICE/KCHUNK

#define NSLOTS (C + T_STEPS)  // 288
#define SEL_THREADS 288       // 9 warps, thread == slot
#define SMEM_D2_BYTES (C * C * 4)        // 147456

// gram smem: one 192-row tile (hi+lo), double buffered
#define ROWB   144                        // bytes per smem row (64 bf16 + 8 pad)
#define BHI_OFF 0
#define BLO_OFF (192 * ROWB)              // 27648
#define STAGE_BYTES (2 * 192 * ROWB)      // 55296
#define GRAM_SMEM_BYTES (2 * STAGE_BYTES) // 110592

// Static device scratch (no allocations allowed)
__device__ __nv_bfloat16 g_xh[(size_t)C * KTOT];     // 38.5 MB, [C][KTOT]
__device__ __nv_bfloat16 g_xl[(size_t)C * KTOT];     // 38.5 MB
__device__ float g_pS[(size_t)NSLICE * C * C];       // 7.2 MB
__device__ float g_pP[(size_t)NSLICE * C * C];       // 7.2 MB
__device__ float g_G[C * C];
__device__ int   g_v1[T_STEPS];
__device__ int   g_v2[T_STEPS];

// ---------------------------------------------------------------------------
// helpers
// ---------------------------------------------------------------------------
__device__ __forceinline__ uint32_t smem_u32(const void* p) {
    return (uint32_t)__cvta_generic_to_shared(p);
}
__device__ __forceinline__ void ldsm_x4(uint32_t* r, uint32_t addr) {
    asm volatile("ldmatrix.sync.aligned.m8n8.x4.shared.b16 {%0,%1,%2,%3}, [%4];"
                 : "=r"(r[0]), "=r"(r[1]), "=r"(r[2]), "=r"(r[3]) : "r"(addr));
}
__device__ __forceinline__ void ldsm_x2(uint32_t* r, uint32_t addr) {
    asm volatile("ldmatrix.sync.aligned.m8n8.x2.shared.b16 {%0,%1}, [%2];"
                 : "=r"(r[0]), "=r"(r[1]) : "r"(addr));
}
__device__ __forceinline__ void mma16816(float* c, const uint32_t* a, const uint32_t* b) {
    asm volatile(
        "mma.sync.aligned.m16n8k16.row.col.f32.bf16.bf16.f32 "
        "{%0,%1,%2,%3}, {%4,%5,%6,%7}, {%8,%9}, {%0,%1,%2,%3};"
        : "+f"(c[0]), "+f"(c[1]), "+f"(c[2]), "+f"(c[3])
        : "r"(a[0]), "r"(a[1]), "r"(a[2]), "r"(a[3]), "r"(b[0]), "r"(b[1]));
}
__device__ __forceinline__ void cp16(uint32_t dst, const void* src) {
    asm volatile("cp.async.cg.shared.global [%0], [%1], 16;" :: "r"(dst), "l"(src));
}
#define CP_COMMIT() asm volatile("cp.async.commit_group;" ::: "memory")
#define CP_WAIT(n)  asm volatile("cp.async.wait_group %0;" :: "n"(n) : "memory")
__device__ __forceinline__ uint32_t pack_bf2(__nv_bfloat16 lo, __nv_bfloat16 hi) {
    return ((uint32_t)__bfloat16_as_ushort(hi) << 16) | (uint32_t)__bfloat16_as_ushort(lo);
}
__device__ __forceinline__ unsigned long long u64min(unsigned long long a,
                                                     unsigned long long b) {
    return a < b ? a : b;
}

// ---------------------------------------------------------------------------
// Kernel 0: convert fp32 x -> hi/lo bf16, transposed to [C][B*HW]
// ---------------------------------------------------------------------------
__global__ __launch_bounds__(256) void convert_kernel(const float* __restrict__ x) {
    const int bc = blockIdx.x;               // b*C + c
    const int bb = bc / C;
    const int cc = bc - bb * C;
    const float4* src = (const float4*)(x + (size_t)bc * HW);
    __nv_bfloat16* dh = g_xh + (size_t)cc * KTOT + bb * HW;
    __nv_bfloat16* dl = g_xl + (size_t)cc * KTOT + bb * HW;
    for (int q = threadIdx.x; q < HW / 4; q += 256) {
        const float4 f = src[q];
        __nv_bfloat16 h0 = __float2bfloat16(f.x);
        __nv_bfloat16 h1 = __float2bfloat16(f.y);
        __nv_bfloat16 h2 = __float2bfloat16(f.z);
        __nv_bfloat16 h3 = __float2bfloat16(f.w);
        __nv_bfloat16 l0 = __float2bfloat16(f.x - __bfloat162float(h0));
        __nv_bfloat16 l1 = __float2bfloat16(f.y - __bfloat162float(h1));
        __nv_bfloat16 l2 = __float2bfloat16(f.z - __bfloat162float(h2));
        __nv_bfloat16 l3 = __float2bfloat16(f.w - __bfloat162float(h3));
        *(uint2*)(dh + q * 4) = make_uint2(pack_bf2(h0, h1), pack_bf2(h2, h3));
        *(uint2*)(dl + q * 4) = make_uint2(pack_bf2(l0, l1), pack_bf2(l2, l3));
    }
}

// ---------------------------------------------------------------------------
// Kernel 1: partial Gram via bf16 mma.sync, 2 products (S=HH^T, P=HL^T).
// (unchanged — measured fast)
// ---------------------------------------------------------------------------
__global__ void __launch_bounds__(256, 1) gram_kernel() {
    extern __shared__ __align__(128) uint8_t sm[];
    const uint32_t sb = smem_u32(sm);
    const int tid  = threadIdx.x;
    const int wid  = tid >> 5;
    const int lane = tid & 31;

    const int bm = blockIdx.x;             // 0..2
    const int s  = blockIdx.y;             // 0..48
    const size_t k0s = (size_t)s * KSLICE;

    const int wm = (wid & 1) * 32;
    const int wn = (wid >> 1) * 48;

    float accS[2][6][4], accP[2][6][4];
#pragma unroll
    for (int ms = 0; ms < 2; ms++)
#pragma unroll
        for (int ns = 0; ns < 6; ns++)
#pragma unroll
            for (int e = 0; e < 4; e++) { accS[ms][ns][e] = 0.0f; accP[ms][ns][e] = 0.0f; }

    const int r_ld = tid >> 3;
    const int g_ld = tid & 7;

    const int aRow = bm * 64 + wm + (lane & 15);
    const uint32_t aOffH = BHI_OFF + aRow * ROWB + (lane >> 4) * 16;
    const uint32_t aOffL = BLO_OFF + aRow * ROWB + (lane >> 4) * 16;
    const int bRow = wn + (lane & 7);
    const uint32_t bOffH = BHI_OFF + bRow * ROWB + ((lane >> 3) & 1) * 16;
    const uint32_t bOffL = BLO_OFF + bRow * ROWB + ((lane >> 3) & 1) * 16;

    {
        const uint32_t st = sb;
        const size_t kb = k0s;
#pragma unroll
        for (int it = 0; it < 6; it++) {
            const int r = r_ld + it * 32;
            const size_t go = (size_t)r * KTOT + kb + g_ld * 8;
            const uint32_t d = st + r * ROWB + g_ld * 16;
            cp16(d + BHI_OFF, g_xh + go);
            cp16(d + BLO_OFF, g_xl + go);
        }
        CP_COMMIT();
    }

    for (int ch = 0; ch < NCHUNK; ch++) {
        if (ch + 1 < NCHUNK) {
            const uint32_t st = sb + ((ch + 1) & 1) * STAGE_BYTES;
            const size_t kb = k0s + (size_t)(ch + 1) * KCHUNK;
#pragma unroll
            for (int it = 0; it < 6; it++) {
                const int r = r_ld + it * 32;
                const size_t go = (size_t)r * KTOT + kb + g_ld * 8;
                const uint32_t d = st + r * ROWB + g_ld * 16;
                cp16(d + BHI_OFF, g_xh + go);
                cp16(d + BLO_OFF, g_xl + go);
            }
            CP_COMMIT();
            CP_WAIT(1);
        } else {
            CP_WAIT(0);
        }
        __syncthreads();

        const uint32_t st = sb + (ch & 1) * STAGE_BYTES;
#pragma unroll
        for (int kk2 = 0; kk2 < 4; kk2++) {
            const uint32_t koff = kk2 * 32;
            uint32_t ahi[2][4], alo[2][4];
#pragma unroll
            for (int ms = 0; ms < 2; ms++) {
                ldsm_x4(ahi[ms], st + aOffH + ms * (16 * ROWB) + koff);
                ldsm_x4(alo[ms], st + aOffL + ms * (16 * ROWB) + koff);
            }
            uint32_t bhi[6][2], blo[6][2];
#pragma unroll
            for (int ns = 0; ns < 6; ns++) {
                ldsm_x2(bhi[ns], st + bOffH + ns * (8 * ROWB) + koff);
                ldsm_x2(blo[ns], st + bOffL + ns * (8 * ROWB) + koff);
            }
#pragma unroll
            for (int ms = 0; ms < 2; ms++)
#pragma unroll
                for (int ns = 0; ns < 6; ns++) {
                    mma16816(accS[ms][ns], ahi[ms], bhi[ns]);
                    mma16816(accP[ms][ns], ahi[ms], blo[ns]);
                }
        }
        __syncthreads();
    }

    float* oS = g_pS + (size_t)s * (C * C);
    float* oP = g_pP + (size_t)s * (C * C);
    const int lr = lane >> 2;
    const int lc = (lane & 3) * 2;
#pragma unroll
    for (int ms = 0; ms < 2; ms++)
#pragma unroll
        for (int ns = 0; ns < 6; ns++) {
            const int row = bm * 64 + wm + ms * 16 + lr;
            const int col = wn + ns * 8 + lc;
            *(float2*)(oS + row * C + col) = make_float2(accS[ms][ns][0], accS[ms][ns][1]);
            *(float2*)(oS + (row + 8) * C + col) = make_float2(accS[ms][ns][2], accS[ms][ns][3]);
            *(float2*)(oP + row * C + col) = make_float2(accP[ms][ns][0], accP[ms][ns][1]);
            *(float2*)(oP + (row + 8) * C + col) = make_float2(accP[ms][ns][2], accP[ms][ns][3]);
        }
}

// ---------------------------------------------------------------------------
// Kernel 2: G = sum_s (S + P) + (sum_s P)^T
// ---------------------------------------------------------------------------
__global__ __launch_bounds__(256) void reduce_kernel() {
    const int gid = blockIdx.x * 256 + threadIdx.x;
    if (gid >= C * C) return;
    const int i = gid / C;
    const int j = gid - i * C;
    float ssum = 0.0f;
#pragma unroll 7
    for (int s = 0; s < NSLICE; s++) {
        const size_t base = (size_t)s * (C * C);
        ssum += g_pS[base + gid] + g_pP[base + gid] + g_pP[base + j * C + i];
    }
    g_G[gid] = ssum;
}

// ---------------------------------------------------------------------------
// Kernel 3: greedy selection — 288 threads (9 warps), thread == slot.
// Register-resident minkey; ONE barrier per step (warpmin double-buffered by
// step parity); fused B+C with local corrections for si/sj/sn staleness.
// key: (dbits<<32)|(row<<9)|partner — u64 min == row-major first-occurrence.
// ---------------------------------------------------------------------------
__global__ __launch_bounds__(SEL_THREADS) void select_kernel() {
    extern __shared__ float sD2[];                       // C*C floats
    __shared__ int s_chan[NSLOTS];
    __shared__ uint32_t s_dead[NSLOTS];                  // 0 alive, ~0 dead
    __shared__ unsigned long long s_initmin[NSLOTS];     // init handoff only
    __shared__ unsigned long long warpmin[2][16];        // [parity][warp]

    const int tid  = threadIdx.x;                        // == slot id
    const int wid  = tid >> 5;                           // 0..8
    const int lane = tid & 31;
    const int wbase = wid * 32;

    // Prologue: build D2 in shared memory from Gram matrix (inline, R12-style).
    for (int id = tid; id < C * C; id += SEL_THREADS) {
        const int i = id / C;
        const int j = id - i * C;
        float d = 0.0f;
        if (i != j) {
            d = g_G[i * C + i] + g_G[j * C + j] - 2.0f * g_G[i * C + j];
            d = fmaxf(d, 0.0f);
        }
        sD2[id] = d;
    }
    s_chan[tid]    = (tid < C) ? tid : 0;
    s_dead[tid]    = (tid < C) ? 0u : 0xffffffffu;
    s_initmin[tid] = ~0ull;
    if (tid < 16) { warpmin[0][tid] = ~0ull; warpmin[1][tid] = ~0ull; }
    __syncthreads();

    // Initial row minima: warp per row, handed off through s_initmin.
    for (int row = wid; row < C - 1; row += 9) {
        const int rowbase = row * C;
        unsigned long long b = ~0ull;                    // (dbits<<32) | sp
        for (int sp = row + 1 + lane; sp < C; sp += 32) {
            const float d = sD2[rowbase + sp];
            b = u64min(b, ((unsigned long long)__float_as_uint(d) << 32) | (unsigned)sp);
        }
        const uint32_t db = (uint32_t)(b >> 32);
        const uint32_t m1 = __reduce_min_sync(0xffffffffu, db);
        const uint32_t cand = (db == m1) ? (uint32_t)b : 0xffffffffu;
        const uint32_t m2 = __reduce_min_sync(0xffffffffu, cand);
        if (lane == 0)
            s_initmin[row] = ((unsigned long long)m1 << 32) |
                             ((unsigned long long)row << 9) | m2;
    }
    __syncthreads();

    unsigned long long mk = s_initmin[tid];              // register-resident key
    int      mychan = (tid < C) ? tid : 0;
    uint32_t mydead = (tid < C) ? 0u : 1u;

    for (int t = 0; t < T_STEPS; t++) {
        const int sn  = C + t;                   // slot appended this step
        const int par = t & 1;

        // ---- Phase A1: per-warp redux on REGISTER keys, one STS ----
        {
            const uint32_t db   = (uint32_t)(mk >> 32);
            const uint32_t lo18 = (uint32_t)mk & 0x3ffffu;
            const uint32_t m1 = __reduce_min_sync(0xffffffffu, db);
            const uint32_t cand = (db == m1) ? lo18 : 0xffffffffu;
            const uint32_t m2 = __reduce_min_sync(0xffffffffu, cand);
            if (lane == 0)
                warpmin[par][wid] = ((unsigned long long)m1 << 32) | m2;
        }
        __syncthreads();                               // the ONLY barrier

        // ---- Phase A2: fan-in over warp minima (1 LDS + redux) ----
        const unsigned long long wv = warpmin[par][lane & 15];
        const uint32_t dbw = (uint32_t)(wv >> 32);
        const uint32_t n1 = __reduce_min_sync(0xffffffffu, dbw);
        const uint32_t candw = (dbw == n1) ? (uint32_t)wv : 0xffffffffu;
        const uint32_t n2 = __reduce_min_sync(0xffffffffu, candw);
        const int si = (int)((n2 >> 9) & 0x1ff);
        const int sj = (int)(n2 & 0x1ff);

        // ---- Phase B: owner updates (registers + own smem slots) ----
        bool dirty = false;
        if (tid == si) {
            g_v1[t] = mychan; mydead = 1u;
            s_dead[tid] = 0xffffffffu; mk = ~0ull;
        } else if (tid == sj) {
            g_v2[t] = mychan; mydead = 1u;
            s_dead[tid] = 0xffffffffu; mk = ~0ull;
        } else if (tid == sn) {
            mydead = 0u; mychan = t;
            s_dead[tid] = 0u; s_chan[tid] = t; mk = ~0ull;
        } else if (!mydead && tid < sn) {
            const int part = (int)(mk & 0x1ff);        // ~0ull -> 0x1ff, no match
            dirty = (part == si) | (part == sj);
            if (!dirty) {
                const float d = sD2[mychan * C + t];   // vs appended chan t
                const unsigned long long nk =
                    ((unsigned long long)__float_as_uint(d) << 32) |
                    ((unsigned long long)tid << 9) | (unsigned)sn;
                mk = u64min(mk, nk);
            }
        }

        // ---- Phase C: warp-cooperative rescans (local corrections) ----
        uint32_t dm = __ballot_sync(0xffffffffu, dirty);
        while (dm) {
            const int l = __ffs(dm) - 1;
            dm &= dm - 1;
            const int row = wbase + l;
            const int rowchan = __shfl_sync(0xffffffffu, mychan, l);
            const int rowb = rowchan * C;
            unsigned long long bb = ~0ull;             // (dbits<<32) | sp
            for (int sp = row + 1 + lane; sp <= sn; sp += 32) {
                // local corrections: si/sj just died, sn just appeared (chan t)
                const int spchan = (sp == sn) ? t : s_chan[sp];
                const uint32_t dead =
                    ((sp == si) | (sp == sj)) ? 0xffffffffu
                                              : ((sp == sn) ? 0u : s_dead[sp]);
                const float d = sD2[rowb + spchan];
                const uint32_t dbits = __float_as_uint(d) | dead;
                bb = u64min(bb, ((unsigned long long)dbits << 32) | (unsigned)sp);
            }
            const uint32_t db2 = (uint32_t)(bb >> 32);
            const uint32_t r1 = __reduce_min_sync(0xffffffffu, db2);
            const uint32_t c2 = (db2 == r1) ? (uint32_t)bb : 0xffffffffu;
            const uint32_t r2 = __reduce_min_sync(0xffffffffu, c2);
            if (lane == l)
                mk = ((unsigned long long)r1 << 32) |
                     ((unsigned long long)row << 9) | (r2 & 0x1ffu);
        }
        // next step's barrier orders this step's s_dead/s_chan writes
        // against the next step's reads; warpmin is parity double-buffered.
    }
}

// ---------------------------------------------------------------------------
// Kernel 4: gather + average -> out[b][t][hw]
// ---------------------------------------------------------------------------
__global__ __launch_bounds__(256) void gather_kernel(const float* __restrict__ x,
                                                     float* __restrict__ out) {
    const int t = blockIdx.x;
    const int b = blockIdx.y;
    const int v1 = g_v1[t];
    const int v2 = g_v2[t];
    const float4* p1 = (const float4*)(x + ((size_t)b * C + v1) * HW);
    const float4* p2 = (const float4*)(x + ((size_t)b * C + v2) * HW);
    float4* po = (float4*)(out + ((size_t)b * T_STEPS + t) * HW);
    for (int q = threadIdx.x; q < HW / 4; q += blockDim.x) {
        const float4 a = p1[q];
        const float4 c = p2[q];
        float4 r;
        r.x = 0.5f * (a.x + c.x);
        r.y = 0.5f * (a.y + c.y);
        r.z = 0.5f * (a.z + c.z);
        r.w = 0.5f * (a.w + c.w);
        po[q] = r;
    }
}

// ---------------------------------------------------------------------------
extern "C" void kernel_launch(void* const* d_in, const int* in_sizes, int n_in,
                              void* d_out, int out_size) {
    const float* x = (const float*)d_in[0];
    float* out = (float*)d_out;

    static bool attr_set = false;
    if (!attr_set) {
        cudaFuncSetAttribute(select_kernel,
                             cudaFuncAttributeMaxDynamicSharedMemorySize,
                             SMEM_D2_BYTES);
        cudaFuncSetAttribute(gram_kernel,
                             cudaFuncAttributeMaxDynamicSharedMemorySize,
                             GRAM_SMEM_BYTES);
        attr_set = true;
    }

    convert_kernel<<<BATCH * C, 256>>>(x);
    gram_kernel<<<dim3(3, NSLICE), 256, GRAM_SMEM_BYTES>>>();
    reduce_kernel<<<144, 256>>>();
    select_kernel<<<1, SEL_THREADS, SMEM_D2_BYTES>>>();
    gather_kernel<<<dim3(T_STEPS, BATCH), 256>>>(x, out);
}

// round 16
// speedup vs baseline: 1.0735x; 1.0735x over previous
#include <cuda_runtime.h>
#include <cuda_bf16.h>
#include <cstdint>

// Problem constants
#define BATCH 32
#define C     192
#define HW    3136            // 56*56
#define CHW   602112          // C*HW
#define KTOT  100352          // BATCH*HW
#define T_STEPS 96
#define NSLICE 49             // K-slices of 2048 (49*2048 = 100352)
#define KSLICE 2048
#define KCHUNK 64             // k per smem chunk (4 x k16)
#define NCHUNK 32             // KSLICE/KCHUNK

#define NSLOTS (C + T_STEPS)  // 288
#define SEL_THREADS 320       // 10 warps
#define SMEM_D2_BYTES (C * C * 4)        // 147456

// gram smem: one 192-row tile (hi+lo), double buffered
#define ROWB   144                        // bytes per smem row (64 bf16 + 8 pad)
#define BHI_OFF 0
#define BLO_OFF (192 * ROWB)              // 27648
#define STAGE_BYTES (2 * 192 * ROWB)      // 55296
#define GRAM_SMEM_BYTES (2 * STAGE_BYTES) // 110592

// Static device scratch (no allocations allowed)
__device__ __nv_bfloat16 g_xh[(size_t)C * KTOT];     // 38.5 MB, [C][KTOT]
__device__ __nv_bfloat16 g_xl[(size_t)C * KTOT];     // 38.5 MB
__device__ float g_pS[(size_t)NSLICE * C * C];       // 7.2 MB
__device__ float g_pP[(size_t)NSLICE * C * C];       // 7.2 MB
__device__ float g_G[C * C];
__device__ int   g_v1[T_STEPS];
__device__ int   g_v2[T_STEPS];

// ---------------------------------------------------------------------------
// helpers
// ---------------------------------------------------------------------------
__device__ __forceinline__ uint32_t smem_u32(const void* p) {
    return (uint32_t)__cvta_generic_to_shared(p);
}
__device__ __forceinline__ void ldsm_x4(uint32_t* r, uint32_t addr) {
    asm volatile("ldmatrix.sync.aligned.m8n8.x4.shared.b16 {%0,%1,%2,%3}, [%4];"
                 : "=r"(r[0]), "=r"(r[1]), "=r"(r[2]), "=r"(r[3]) : "r"(addr));
}
__device__ __forceinline__ void ldsm_x2(uint32_t* r, uint32_t addr) {
    asm volatile("ldmatrix.sync.aligned.m8n8.x2.shared.b16 {%0,%1}, [%2];"
                 : "=r"(r[0]), "=r"(r[1]) : "r"(addr));
}
__device__ __forceinline__ void mma16816(float* c, const uint32_t* a, const uint32_t* b) {
    asm volatile(
        "mma.sync.aligned.m16n8k16.row.col.f32.bf16.bf16.f32 "
        "{%0,%1,%2,%3}, {%4,%5,%6,%7}, {%8,%9}, {%0,%1,%2,%3};"
        : "+f"(c[0]), "+f"(c[1]), "+f"(c[2]), "+f"(c[3])
        : "r"(a[0]), "r"(a[1]), "r"(a[2]), "r"(a[3]), "r"(b[0]), "r"(b[1]));
}
__device__ __forceinline__ void cp16(uint32_t dst, const void* src) {
    asm volatile("cp.async.cg.shared.global [%0], [%1], 16;" :: "r"(dst), "l"(src));
}
#define CP_COMMIT() asm volatile("cp.async.commit_group;" ::: "memory")
#define CP_WAIT(n)  asm volatile("cp.async.wait_group %0;" :: "n"(n) : "memory")
__device__ __forceinline__ uint32_t pack_bf2(__nv_bfloat16 lo, __nv_bfloat16 hi) {
    return ((uint32_t)__bfloat16_as_ushort(hi) << 16) | (uint32_t)__bfloat16_as_ushort(lo);
}
__device__ __forceinline__ unsigned long long u64min(unsigned long long a,
                                                     unsigned long long b) {
    return a < b ? a : b;
}

// ---------------------------------------------------------------------------
// Kernel 0: convert fp32 x -> hi/lo bf16, transposed to [C][B*HW]
// ---------------------------------------------------------------------------
__global__ __launch_bounds__(256) void convert_kernel(const float* __restrict__ x) {
    const int bc = blockIdx.x;               // b*C + c
    const int bb = bc / C;
    const int cc = bc - bb * C;
    const float4* src = (const float4*)(x + (size_t)bc * HW);
    __nv_bfloat16* dh = g_xh + (size_t)cc * KTOT + bb * HW;
    __nv_bfloat16* dl = g_xl + (size_t)cc * KTOT + bb * HW;
    for (int q = threadIdx.x; q < HW / 4; q += 256) {
        const float4 f = src[q];
        __nv_bfloat16 h0 = __float2bfloat16(f.x);
        __nv_bfloat16 h1 = __float2bfloat16(f.y);
        __nv_bfloat16 h2 = __float2bfloat16(f.z);
        __nv_bfloat16 h3 = __float2bfloat16(f.w);
        __nv_bfloat16 l0 = __float2bfloat16(f.x - __bfloat162float(h0));
        __nv_bfloat16 l1 = __float2bfloat16(f.y - __bfloat162float(h1));
        __nv_bfloat16 l2 = __float2bfloat16(f.z - __bfloat162float(h2));
        __nv_bfloat16 l3 = __float2bfloat16(f.w - __bfloat162float(h3));
        *(uint2*)(dh + q * 4) = make_uint2(pack_bf2(h0, h1), pack_bf2(h2, h3));
        *(uint2*)(dl + q * 4) = make_uint2(pack_bf2(l0, l1), pack_bf2(l2, l3));
    }
}

// ---------------------------------------------------------------------------
// Kernel 1: partial Gram via bf16 mma.sync, 2 products (S=HH^T, P=HL^T).
// Block (bm, s): rows [bm*96, bm*96+96) x all 192 cols, K slice s (2048).
// 2 M-blocks (was 3): B-tile re-read redundancy 3x -> 2x (231 -> 154 MB).
// One smem tile (192 rows, hi+lo), A fragments read from the B tile.
// ---------------------------------------------------------------------------
__global__ void __launch_bounds__(256, 1) gram_kernel() {
    extern __shared__ __align__(128) uint8_t sm[];
    const uint32_t sb = smem_u32(sm);
    const int tid  = threadIdx.x;
    const int wid  = tid >> 5;
    const int lane = tid & 31;

    const int bm = blockIdx.x;             // 0..1
    const int s  = blockIdx.y;             // 0..48
    const size_t k0s = (size_t)s * KSLICE;

    const int wm = (wid & 1) * 48;         // warp M offset within 96
    const int wn = (wid >> 1) * 48;        // warp N offset (0,48,96,144)

    float accS[3][6][4], accP[3][6][4];
#pragma unroll
    for (int ms = 0; ms < 3; ms++)
#pragma unroll
        for (int ns = 0; ns < 6; ns++)
#pragma unroll
            for (int e = 0; e < 4; e++) { accS[ms][ns][e] = 0.0f; accP[ms][ns][e] = 0.0f; }

    const int r_ld = tid >> 3;
    const int g_ld = tid & 7;

    const int aRow = bm * 96 + wm + (lane & 15);
    const uint32_t aOffH = BHI_OFF + aRow * ROWB + (lane >> 4) * 16;
    const uint32_t aOffL = BLO_OFF + aRow * ROWB + (lane >> 4) * 16;
    const int bRow = wn + (lane & 7);
    const uint32_t bOffH = BHI_OFF + bRow * ROWB + ((lane >> 3) & 1) * 16;
    const uint32_t bOffL = BLO_OFF + bRow * ROWB + ((lane >> 3) & 1) * 16;

    {
        const uint32_t st = sb;
        const size_t kb = k0s;
#pragma unroll
        for (int it = 0; it < 6; it++) {
            const int r = r_ld + it * 32;
            const size_t go = (size_t)r * KTOT + kb + g_ld * 8;
            const uint32_t d = st + r * ROWB + g_ld * 16;
            cp16(d + BHI_OFF, g_xh + go);
            cp16(d + BLO_OFF, g_xl + go);
        }
        CP_COMMIT();
    }

    for (int ch = 0; ch < NCHUNK; ch++) {
        if (ch + 1 < NCHUNK) {
            const uint32_t st = sb + ((ch + 1) & 1) * STAGE_BYTES;
            const size_t kb = k0s + (size_t)(ch + 1) * KCHUNK;
#pragma unroll
            for (int it = 0; it < 6; it++) {
                const int r = r_ld + it * 32;
                const size_t go = (size_t)r * KTOT + kb + g_ld * 8;
                const uint32_t d = st + r * ROWB + g_ld * 16;
                cp16(d + BHI_OFF, g_xh + go);
                cp16(d + BLO_OFF, g_xl + go);
            }
            CP_COMMIT();
            CP_WAIT(1);
        } else {
            CP_WAIT(0);
        }
        __syncthreads();

        const uint32_t st = sb + (ch & 1) * STAGE_BYTES;
#pragma unroll
        for (int kk2 = 0; kk2 < 4; kk2++) {
            const uint32_t koff = kk2 * 32;
            uint32_t ahi[3][4], alo[3][4];
#pragma unroll
            for (int ms = 0; ms < 3; ms++) {
                ldsm_x4(ahi[ms], st + aOffH + ms * (16 * ROWB) + koff);
                ldsm_x4(alo[ms], st + aOffL + ms * (16 * ROWB) + koff);
            }
            uint32_t bhi[6][2], blo[6][2];
#pragma unroll
            for (int ns = 0; ns < 6; ns++) {
                ldsm_x2(bhi[ns], st + bOffH + ns * (8 * ROWB) + koff);
                ldsm_x2(blo[ns], st + bOffL + ns * (8 * ROWB) + koff);
            }
#pragma unroll
            for (int ms = 0; ms < 3; ms++)
#pragma unroll
                for (int ns = 0; ns < 6; ns++) {
                    mma16816(accS[ms][ns], ahi[ms], bhi[ns]);
                    mma16816(accP[ms][ns], ahi[ms], blo[ns]);
                }
        }
        __syncthreads();
    }

    float* oS = g_pS + (size_t)s * (C * C);
    float* oP = g_pP + (size_t)s * (C * C);
    const int lr = lane >> 2;
    const int lc = (lane & 3) * 2;
#pragma unroll
    for (int ms = 0; ms < 3; ms++)
#pragma unroll
        for (int ns = 0; ns < 6; ns++) {
            const int row = bm * 96 + wm + ms * 16 + lr;
            const int col = wn + ns * 8 + lc;
            *(float2*)(oS + row * C + col) = make_float2(accS[ms][ns][0], accS[ms][ns][1]);
            *(float2*)(oS + (row + 8) * C + col) = make_float2(accS[ms][ns][2], accS[ms][ns][3]);
            *(float2*)(oP + row * C + col) = make_float2(accP[ms][ns][0], accP[ms][ns][1]);
            *(float2*)(oP + (row + 8) * C + col) = make_float2(accP[ms][ns][2], accP[ms][ns][3]);
        }
}

// ---------------------------------------------------------------------------
// Kernel 2: G = sum_s (S + P) + (sum_s P)^T
// ---------------------------------------------------------------------------
__global__ __launch_bounds__(256) void reduce_kernel() {
    const int gid = blockIdx.x * 256 + threadIdx.x;
    if (gid >= C * C) return;
    const int i = gid / C;
    const int j = gid - i * C;
    float ssum = 0.0f;
#pragma unroll 7
    for (int s = 0; s < NSLICE; s++) {
        const size_t base = (size_t)s * (C * C);
        ssum += g_pS[base + gid] + g_pP[base + gid] + g_pP[base + j * C + i];
    }
    g_G[gid] = ssum;
}

// ---------------------------------------------------------------------------
// Kernel 3: greedy selection — EXACT R12 version (measured best: 121.7us).
// 320 threads (10 warps), per-row minima, argmin via two-stage redux.sync +
// STS/LDS fan-in (no shared atomics for argmin). 3 block barriers per step.
// minkey: (dbits<<32) | (row<<9) | partner — lexicographic u64 min
// == row-major first-occurrence argmin.
// ---------------------------------------------------------------------------
__global__ __launch_bounds__(SEL_THREADS) void select_kernel() {
    extern __shared__ float sD2[];                       // C*C floats
    __shared__ int  s_chan[NSLOTS];
    __shared__ uint32_t s_dead[NSLOTS];                  // 0 alive, ~0 dead
    __shared__ unsigned long long s_minkey[NSLOTS];
    __shared__ unsigned long long warpmin[16];           // [10..15] stay ~0
    __shared__ int s_dirty[2][NSLOTS];
    __shared__ int s_cnt[2];

    const int tid  = threadIdx.x;
    const int wid  = tid >> 5;          // 0..9
    const int lane = tid & 31;

    // Build D2 in shared memory from Gram matrix.
    for (int id = tid; id < C * C; id += SEL_THREADS) {
        const int i = id / C;
        const int j = id - i * C;
        float d = 0.0f;
        if (i != j) {
            d = g_G[i * C + i] + g_G[j * C + j] - 2.0f * g_G[i * C + j];
            d = fmaxf(d, 0.0f);
        }
        sD2[id] = d;
    }
    if (tid < NSLOTS) {
        s_chan[tid]   = (tid < C) ? tid : 0;
        s_dead[tid]   = (tid < C) ? 0u : 0xffffffffu;
        s_minkey[tid] = ~0ull;
    }
    if (tid < 16) warpmin[tid] = ~0ull;
    if (tid == 0) { s_cnt[0] = 0; s_cnt[1] = 0; }
    __syncthreads();

    // Initial row minima: warp per row (two-stage redux).
    for (int row = wid; row < C - 1; row += 10) {
        const int rowbase = row * C;
        unsigned long long b = ~0ull;                    // (dbits<<32) | sp
        for (int sp = row + 1 + lane; sp < C; sp += 32) {
            const float d = sD2[rowbase + sp];
            b = u64min(b, ((unsigned long long)__float_as_uint(d) << 32) | (unsigned)sp);
        }
        const uint32_t db = (uint32_t)(b >> 32);
        const uint32_t m1 = __reduce_min_sync(0xffffffffu, db);
        const uint32_t cand = (db == m1) ? (uint32_t)b : 0xffffffffu;
        const uint32_t m2 = __reduce_min_sync(0xffffffffu, cand);
        if (lane == 0)
            s_minkey[row] = ((unsigned long long)m1 << 32) |
                            ((unsigned long long)row << 9) | m2;
    }
    __syncthreads();

    for (int t = 0; t < T_STEPS; t++) {
        const int cur = t & 1, nxt = cur ^ 1;
        const int sn = C + t;                    // slot appended this step

        // ---- Phase A1: per-warp min of the 288 keys (one slot per thread) ----
        const unsigned long long mk = (tid < NSLOTS) ? s_minkey[tid] : ~0ull;
        {
            const uint32_t db   = (uint32_t)(mk >> 32);
            const uint32_t lo18 = (uint32_t)mk & 0x3ffffu;
            const uint32_t m1 = __reduce_min_sync(0xffffffffu, db);
            const uint32_t cand = (db == m1) ? lo18 : 0xffffffffu;
            const uint32_t m2 = __reduce_min_sync(0xffffffffu, cand);
            if (lane == 0)
                warpmin[wid] = ((unsigned long long)m1 << 32) | m2;
        }
        __syncthreads();                               // barrier 1

        // ---- Phase A2: every thread reduces the 16 warp minima (no atomics) ----
        unsigned long long wv = warpmin[lane & 15];
        {
            const uint32_t db = (uint32_t)(wv >> 32);
            const uint32_t m1 = __reduce_min_sync(0xffffffffu, db);
            const uint32_t cand = (db == m1) ? (uint32_t)wv : 0xffffffffu;
            const uint32_t m2 = __reduce_min_sync(0xffffffffu, cand);
            wv = ((unsigned long long)m1 << 32) | m2;
        }
        const int si = (int)((wv >> 9) & 0x1ff);
        const int sj = (int)(wv & 0x1ff);

        // ---- Phase B: distributed bookkeeping + O(1) updates + dirty list ----
        if (tid == si) { g_v1[t] = s_chan[si]; s_dead[si] = 0xffffffffu; s_minkey[si] = ~0ull; }
        if (tid == sj) { g_v2[t] = s_chan[sj]; s_dead[sj] = 0xffffffffu; s_minkey[sj] = ~0ull; }
        if (tid == sn) { s_dead[sn] = 0u; s_chan[sn] = t; s_minkey[sn] = ~0ull; }
        if (tid == SEL_THREADS - 1) s_cnt[nxt] = 0;
        if (tid < sn && tid != si && tid != sj && s_dead[tid] == 0u) {
            const int part = (int)(mk & 0x1ff);        // ~0ull -> 0x1ff (never matches)
            if (part == si || part == sj) {
                const int k = atomicAdd(&s_cnt[cur], 1);
                s_dirty[cur][k] = tid;
            } else {
                const float d = sD2[s_chan[tid] * C + t];   // vs appended chan t
                const unsigned long long nk =
                    ((unsigned long long)__float_as_uint(d) << 32) |
                    ((unsigned long long)tid << 9) | (unsigned)sn;
                if (nk < mk) s_minkey[tid] = nk;
            }
        }
        __syncthreads();                               // barrier 2

        // ---- Phase C: warp-per-dirty-row rescans (dead-mask OR, redux) ----
        const int cnt = s_cnt[cur];
        for (int k = wid; k < cnt; k += 10) {
            const int row = s_dirty[cur][k];
            const int rowbase = s_chan[row] * C;
            unsigned long long b = ~0ull;              // (dbits<<32) | sp
            for (int sp = row + 1 + lane; sp <= sn; sp += 32) {
                const float d = sD2[rowbase + s_chan[sp]];
                const uint32_t dbits = __float_as_uint(d) | s_dead[sp];
                b = u64min(b, ((unsigned long long)dbits << 32) | (unsigned)sp);
            }
            const uint32_t db2 = (uint32_t)(b >> 32);
            const uint32_t n1 = __reduce_min_sync(0xffffffffu, db2);
            const uint32_t c2 = (db2 == n1) ? (uint32_t)b : 0xffffffffu;
            const uint32_t n2 = __reduce_min_sync(0xffffffffu, c2);
            if (lane == 0)
                s_minkey[row] = ((unsigned long long)n1 << 32) |
                                ((unsigned long long)row << 9) | (n2 & 0x1ffu);
        }
        __syncthreads();                               // barrier 3
    }
}

// ---------------------------------------------------------------------------
// Kernel 4: gather + average -> out[b][t][hw]
// ---------------------------------------------------------------------------
__global__ __launch_bounds__(256) void gather_kernel(const float* __restrict__ x,
                                                     float* __restrict__ out) {
    const int t = blockIdx.x;
    const int b = blockIdx.y;
    const int v1 = g_v1[t];
    const int v2 = g_v2[t];
    const float4* p1 = (const float4*)(x + ((size_t)b * C + v1) * HW);
    const float4* p2 = (const float4*)(x + ((size_t)b * C + v2) * HW);
    float4* po = (float4*)(out + ((size_t)b * T_STEPS + t) * HW);
    for (int q = threadIdx.x; q < HW / 4; q += blockDim.x) {
        const float4 a = p1[q];
        const float4 c = p2[q];
        float4 r;
        r.x = 0.5f * (a.x + c.x);
        r.y = 0.5f * (a.y + c.y);
        r.z = 0.5f * (a.z + c.z);
        r.w = 0.5f * (a.w + c.w);
        po[q] = r;
    }
}

// ---------------------------------------------------------------------------
extern "C" void kernel_launch(void* const* d_in, const int* in_sizes, int n_in,
                              void* d_out, int out_size) {
    const float* x = (const float*)d_in[0];
    float* out = (float*)d_out;

    static bool attr_set = false;
    if (!attr_set) {
        cudaFuncSetAttribute(select_kernel,
                             cudaFuncAttributeMaxDynamicSharedMemorySize,
                             SMEM_D2_BYTES);
        cudaFuncSetAttribute(gram_kernel,
                             cudaFuncAttributeMaxDynamicSharedMemorySize,
                             GRAM_SMEM_BYTES);
        attr_set = true;
    }

    convert_kernel<<<BATCH * C, 256>>>(x);
    gram_kernel<<<dim3(2, NSLICE), 256, GRAM_SMEM_BYTES>>>();
    reduce_kernel<<<144, 256>>>();
    select_kernel<<<1, SEL_THREADS, SMEM_D2_BYTES>>>();
    gather_kernel<<<dim3(T_STEPS, BATCH), 256>>>(x, out);
}

// round 17
// speedup vs baseline: 1.1472x; 1.0686x over previous
#include <cuda_runtime.h>
#include <cuda_bf16.h>
#include <cstdint>

// Problem constants
#define BATCH 32
#define C     192
#define HW    3136            // 56*56
#define CHW   602112          // C*HW
#define KTOT  100352          // BATCH*HW
#define T_STEPS 96
#define NSLICE 49             // K-slices of 2048 (49*2048 = 100352)
#define KSLICE 2048
#define KCHUNK 64             // k per smem chunk (4 x k16)
#define NCHUNK 32             // KSLICE/KCHUNK

#define NSLOTS (C + T_STEPS)  // 288
#define SEL_THREADS 320       // 10 warps
#define SMEM_D2_BYTES (C * C * 4)        // 147456

// gram smem: one 192-row tile (hi+lo), double buffered
#define ROWB   144                        // bytes per smem row (64 bf16 + 8 pad)
#define BHI_OFF 0
#define BLO_OFF (192 * ROWB)              // 27648
#define STAGE_BYTES (2 * 192 * ROWB)      // 55296
#define GRAM_SMEM_BYTES (2 * STAGE_BYTES) // 110592

// Static device scratch (no allocations allowed)
__device__ __nv_bfloat16 g_xh[(size_t)C * KTOT];     // 38.5 MB, [C][KTOT]
__device__ __nv_bfloat16 g_xl[(size_t)C * KTOT];     // 38.5 MB
__device__ float g_pS[(size_t)NSLICE * C * C];       // 7.2 MB
__device__ float g_pP[(size_t)NSLICE * C * C];       // 7.2 MB
__device__ float g_G[C * C];
__device__ int   g_v1[T_STEPS];
__device__ int   g_v2[T_STEPS];

// ---------------------------------------------------------------------------
// helpers
// ---------------------------------------------------------------------------
__device__ __forceinline__ uint32_t smem_u32(const void* p) {
    return (uint32_t)__cvta_generic_to_shared(p);
}
__device__ __forceinline__ void ldsm_x4(uint32_t* r, uint32_t addr) {
    asm volatile("ldmatrix.sync.aligned.m8n8.x4.shared.b16 {%0,%1,%2,%3}, [%4];"
                 : "=r"(r[0]), "=r"(r[1]), "=r"(r[2]), "=r"(r[3]) : "r"(addr));
}
__device__ __forceinline__ void ldsm_x2(uint32_t* r, uint32_t addr) {
    asm volatile("ldmatrix.sync.aligned.m8n8.x2.shared.b16 {%0,%1}, [%2];"
                 : "=r"(r[0]), "=r"(r[1]) : "r"(addr));
}
__device__ __forceinline__ void mma16816(float* c, const uint32_t* a, const uint32_t* b) {
    asm volatile(
        "mma.sync.aligned.m16n8k16.row.col.f32.bf16.bf16.f32 "
        "{%0,%1,%2,%3}, {%4,%5,%6,%7}, {%8,%9}, {%0,%1,%2,%3};"
        : "+f"(c[0]), "+f"(c[1]), "+f"(c[2]), "+f"(c[3])
        : "r"(a[0]), "r"(a[1]), "r"(a[2]), "r"(a[3]), "r"(b[0]), "r"(b[1]));
}
__device__ __forceinline__ void cp16(uint32_t dst, const void* src) {
    asm volatile("cp.async.cg.shared.global [%0], [%1], 16;" :: "r"(dst), "l"(src));
}
#define CP_COMMIT() asm volatile("cp.async.commit_group;" ::: "memory")
#define CP_WAIT(n)  asm volatile("cp.async.wait_group %0;" :: "n"(n) : "memory")
__device__ __forceinline__ uint32_t pack_bf2(__nv_bfloat16 lo, __nv_bfloat16 hi) {
    return ((uint32_t)__bfloat16_as_ushort(hi) << 16) | (uint32_t)__bfloat16_as_ushort(lo);
}
__device__ __forceinline__ unsigned long long u64min(unsigned long long a,
                                                     unsigned long long b) {
    return a < b ? a : b;
}

// ---------------------------------------------------------------------------
// Kernel 0: convert fp32 x -> hi/lo bf16, transposed to [C][B*HW]
// ---------------------------------------------------------------------------
__global__ __launch_bounds__(256) void convert_kernel(const float* __restrict__ x) {
    const int bc = blockIdx.x;               // b*C + c
    const int bb = bc / C;
    const int cc = bc - bb * C;
    const float4* src = (const float4*)(x + (size_t)bc * HW);
    __nv_bfloat16* dh = g_xh + (size_t)cc * KTOT + bb * HW;
    __nv_bfloat16* dl = g_xl + (size_t)cc * KTOT + bb * HW;
    for (int q = threadIdx.x; q < HW / 4; q += 256) {
        const float4 f = src[q];
        __nv_bfloat16 h0 = __float2bfloat16(f.x);
        __nv_bfloat16 h1 = __float2bfloat16(f.y);
        __nv_bfloat16 h2 = __float2bfloat16(f.z);
        __nv_bfloat16 h3 = __float2bfloat16(f.w);
        __nv_bfloat16 l0 = __float2bfloat16(f.x - __bfloat162float(h0));
        __nv_bfloat16 l1 = __float2bfloat16(f.y - __bfloat162float(h1));
        __nv_bfloat16 l2 = __float2bfloat16(f.z - __bfloat162float(h2));
        __nv_bfloat16 l3 = __float2bfloat16(f.w - __bfloat162float(h3));
        *(uint2*)(dh + q * 4) = make_uint2(pack_bf2(h0, h1), pack_bf2(h2, h3));
        *(uint2*)(dl + q * 4) = make_uint2(pack_bf2(l0, l1), pack_bf2(l2, l3));
    }
}

// ---------------------------------------------------------------------------
// Kernel 1: partial Gram via bf16 mma.sync, 2 products (S=HH^T, P=HL^T).
// EXACT R12 version (3 M-blocks of 64 rows; measured at the tensor floor).
// ---------------------------------------------------------------------------
__global__ void __launch_bounds__(256, 1) gram_kernel() {
    extern __shared__ __align__(128) uint8_t sm[];
    const uint32_t sb = smem_u32(sm);
    const int tid  = threadIdx.x;
    const int wid  = tid >> 5;
    const int lane = tid & 31;

    const int bm = blockIdx.x;             // 0..2
    const int s  = blockIdx.y;             // 0..48
    const size_t k0s = (size_t)s * KSLICE;

    const int wm = (wid & 1) * 32;
    const int wn = (wid >> 1) * 48;

    float accS[2][6][4], accP[2][6][4];
#pragma unroll
    for (int ms = 0; ms < 2; ms++)
#pragma unroll
        for (int ns = 0; ns < 6; ns++)
#pragma unroll
            for (int e = 0; e < 4; e++) { accS[ms][ns][e] = 0.0f; accP[ms][ns][e] = 0.0f; }

    const int r_ld = tid >> 3;
    const int g_ld = tid & 7;

    const int aRow = bm * 64 + wm + (lane & 15);
    const uint32_t aOffH = BHI_OFF + aRow * ROWB + (lane >> 4) * 16;
    const uint32_t aOffL = BLO_OFF + aRow * ROWB + (lane >> 4) * 16;
    const int bRow = wn + (lane & 7);
    const uint32_t bOffH = BHI_OFF + bRow * ROWB + ((lane >> 3) & 1) * 16;
    const uint32_t bOffL = BLO_OFF + bRow * ROWB + ((lane >> 3) & 1) * 16;

    {
        const uint32_t st = sb;
        const size_t kb = k0s;
#pragma unroll
        for (int it = 0; it < 6; it++) {
            const int r = r_ld + it * 32;
            const size_t go = (size_t)r * KTOT + kb + g_ld * 8;
            const uint32_t d = st + r * ROWB + g_ld * 16;
            cp16(d + BHI_OFF, g_xh + go);
            cp16(d + BLO_OFF, g_xl + go);
        }
        CP_COMMIT();
    }

    for (int ch = 0; ch < NCHUNK; ch++) {
        if (ch + 1 < NCHUNK) {
            const uint32_t st = sb + ((ch + 1) & 1) * STAGE_BYTES;
            const size_t kb = k0s + (size_t)(ch + 1) * KCHUNK;
#pragma unroll
            for (int it = 0; it < 6; it++) {
                const int r = r_ld + it * 32;
                const size_t go = (size_t)r * KTOT + kb + g_ld * 8;
                const uint32_t d = st + r * ROWB + g_ld * 16;
                cp16(d + BHI_OFF, g_xh + go);
                cp16(d + BLO_OFF, g_xl + go);
            }
            CP_COMMIT();
            CP_WAIT(1);
        } else {
            CP_WAIT(0);
        }
        __syncthreads();

        const uint32_t st = sb + (ch & 1) * STAGE_BYTES;
#pragma unroll
        for (int kk2 = 0; kk2 < 4; kk2++) {
            const uint32_t koff = kk2 * 32;
            uint32_t ahi[2][4], alo[2][4];
#pragma unroll
            for (int ms = 0; ms < 2; ms++) {
                ldsm_x4(ahi[ms], st + aOffH + ms * (16 * ROWB) + koff);
                ldsm_x4(alo[ms], st + aOffL + ms * (16 * ROWB) + koff);
            }
            uint32_t bhi[6][2], blo[6][2];
#pragma unroll
            for (int ns = 0; ns < 6; ns++) {
                ldsm_x2(bhi[ns], st + bOffH + ns * (8 * ROWB) + koff);
                ldsm_x2(blo[ns], st + bOffL + ns * (8 * ROWB) + koff);
            }
#pragma unroll
            for (int ms = 0; ms < 2; ms++)
#pragma unroll
                for (int ns = 0; ns < 6; ns++) {
                    mma16816(accS[ms][ns], ahi[ms], bhi[ns]);
                    mma16816(accP[ms][ns], ahi[ms], blo[ns]);
                }
        }
        __syncthreads();
    }

    float* oS = g_pS + (size_t)s * (C * C);
    float* oP = g_pP + (size_t)s * (C * C);
    const int lr = lane >> 2;
    const int lc = (lane & 3) * 2;
#pragma unroll
    for (int ms = 0; ms < 2; ms++)
#pragma unroll
        for (int ns = 0; ns < 6; ns++) {
            const int row = bm * 64 + wm + ms * 16 + lr;
            const int col = wn + ns * 8 + lc;
            *(float2*)(oS + row * C + col) = make_float2(accS[ms][ns][0], accS[ms][ns][1]);
            *(float2*)(oS + (row + 8) * C + col) = make_float2(accS[ms][ns][2], accS[ms][ns][3]);
            *(float2*)(oP + row * C + col) = make_float2(accP[ms][ns][0], accP[ms][ns][1]);
            *(float2*)(oP + (row + 8) * C + col) = make_float2(accP[ms][ns][2], accP[ms][ns][3]);
        }
}

// ---------------------------------------------------------------------------
// Kernel 2: G = sum_s (S + P) + (sum_s P)^T
// ---------------------------------------------------------------------------
__global__ __launch_bounds__(256) void reduce_kernel() {
    const int gid = blockIdx.x * 256 + threadIdx.x;
    if (gid >= C * C) return;
    const int i = gid / C;
    const int j = gid - i * C;
    float ssum = 0.0f;
#pragma unroll 7
    for (int s = 0; s < NSLICE; s++) {
        const size_t base = (size_t)s * (C * C);
        ssum += g_pS[base + gid] + g_pP[base + gid] + g_pP[base + j * C + i];
    }
    g_G[gid] = ssum;
}

// ---------------------------------------------------------------------------
// Kernel 3: greedy selection — EXACT R12 algorithm (measured best select).
// Launched with grid=148: block 0 does all the work; blocks 1..147 exit
// immediately. This defeats the documented single-CTA issue throttle
// (pSmIssueThrottleCtrl: +28% at low grid, vanishes at grid>=148) and keeps
// DVFS from idling the chip around one resident CTA.
// ---------------------------------------------------------------------------
__global__ __launch_bounds__(SEL_THREADS) void select_kernel() {
    if (blockIdx.x != 0) return;             // dummy blocks: occupy grid, exit

    extern __shared__ float sD2[];                       // C*C floats
    __shared__ int  s_chan[NSLOTS];
    __shared__ uint32_t s_dead[NSLOTS];                  // 0 alive, ~0 dead
    __shared__ unsigned long long s_minkey[NSLOTS];
    __shared__ unsigned long long warpmin[16];           // [10..15] stay ~0
    __shared__ int s_dirty[2][NSLOTS];
    __shared__ int s_cnt[2];

    const int tid  = threadIdx.x;
    const int wid  = tid >> 5;          // 0..9
    const int lane = tid & 31;

    // Build D2 in shared memory from Gram matrix.
    for (int id = tid; id < C * C; id += SEL_THREADS) {
        const int i = id / C;
        const int j = id - i * C;
        float d = 0.0f;
        if (i != j) {
            d = g_G[i * C + i] + g_G[j * C + j] - 2.0f * g_G[i * C + j];
            d = fmaxf(d, 0.0f);
        }
        sD2[id] = d;
    }
    if (tid < NSLOTS) {
        s_chan[tid]   = (tid < C) ? tid : 0;
        s_dead[tid]   = (tid < C) ? 0u : 0xffffffffu;
        s_minkey[tid] = ~0ull;
    }
    if (tid < 16) warpmin[tid] = ~0ull;
    if (tid == 0) { s_cnt[0] = 0; s_cnt[1] = 0; }
    __syncthreads();

    // Initial row minima: warp per row (two-stage redux).
    for (int row = wid; row < C - 1; row += 10) {
        const int rowbase = row * C;
        unsigned long long b = ~0ull;                    // (dbits<<32) | sp
        for (int sp = row + 1 + lane; sp < C; sp += 32) {
            const float d = sD2[rowbase + sp];
            b = u64min(b, ((unsigned long long)__float_as_uint(d) << 32) | (unsigned)sp);
        }
        const uint32_t db = (uint32_t)(b >> 32);
        const uint32_t m1 = __reduce_min_sync(0xffffffffu, db);
        const uint32_t cand = (db == m1) ? (uint32_t)b : 0xffffffffu;
        const uint32_t m2 = __reduce_min_sync(0xffffffffu, cand);
        if (lane == 0)
            s_minkey[row] = ((unsigned long long)m1 << 32) |
                            ((unsigned long long)row << 9) | m2;
    }
    __syncthreads();

    for (int t = 0; t < T_STEPS; t++) {
        const int cur = t & 1, nxt = cur ^ 1;
        const int sn = C + t;                    // slot appended this step

        // ---- Phase A1: per-warp min of the 288 keys (one slot per thread) ----
        const unsigned long long mk = (tid < NSLOTS) ? s_minkey[tid] : ~0ull;
        {
            const uint32_t db   = (uint32_t)(mk >> 32);
            const uint32_t lo18 = (uint32_t)mk & 0x3ffffu;
            const uint32_t m1 = __reduce_min_sync(0xffffffffu, db);
            const uint32_t cand = (db == m1) ? lo18 : 0xffffffffu;
            const uint32_t m2 = __reduce_min_sync(0xffffffffu, cand);
            if (lane == 0)
                warpmin[wid] = ((unsigned long long)m1 << 32) | m2;
        }
        __syncthreads();                               // barrier 1

        // ---- Phase A2: every thread reduces the 16 warp minima (no atomics) ----
        unsigned long long wv = warpmin[lane & 15];
        {
            const uint32_t db = (uint32_t)(wv >> 32);
            const uint32_t m1 = __reduce_min_sync(0xffffffffu, db);
            const uint32_t cand = (db == m1) ? (uint32_t)wv : 0xffffffffu;
            const uint32_t m2 = __reduce_min_sync(0xffffffffu, cand);
            wv = ((unsigned long long)m1 << 32) | m2;
        }
        const int si = (int)((wv >> 9) & 0x1ff);
        const int sj = (int)(wv & 0x1ff);

        // ---- Phase B: distributed bookkeeping + O(1) updates + dirty list ----
        if (tid == si) { g_v1[t] = s_chan[si]; s_dead[si] = 0xffffffffu; s_minkey[si] = ~0ull; }
        if (tid == sj) { g_v2[t] = s_chan[sj]; s_dead[sj] = 0xffffffffu; s_minkey[sj] = ~0ull; }
        if (tid == sn) { s_dead[sn] = 0u; s_chan[sn] = t; s_minkey[sn] = ~0ull; }
        if (tid == SEL_THREADS - 1) s_cnt[nxt] = 0;
        if (tid < sn && tid != si && tid != sj && s_dead[tid] == 0u) {
            const int part = (int)(mk & 0x1ff);        // ~0ull -> 0x1ff (never matches)
            if (part == si || part == sj) {
                const int k = atomicAdd(&s_cnt[cur], 1);
                s_dirty[cur][k] = tid;
            } else {
                const float d = sD2[s_chan[tid] * C + t];   // vs appended chan t
                const unsigned long long nk =
                    ((unsigned long long)__float_as_uint(d) << 32) |
                    ((unsigned long long)tid << 9) | (unsigned)sn;
                if (nk < mk) s_minkey[tid] = nk;
            }
        }
        __syncthreads();                               // barrier 2

        // ---- Phase C: warp-per-dirty-row rescans (dead-mask OR, redux) ----
        const int cnt = s_cnt[cur];
        for (int k = wid; k < cnt; k += 10) {
            const int row = s_dirty[cur][k];
            const int rowbase = s_chan[row] * C;
            unsigned long long b = ~0ull;              // (dbits<<32) | sp
            for (int sp = row + 1 + lane; sp <= sn; sp += 32) {
                const float d = sD2[rowbase + s_chan[sp]];
                const uint32_t dbits = __float_as_uint(d) | s_dead[sp];
                b = u64min(b, ((unsigned long long)dbits << 32) | (unsigned)sp);
            }
            const uint32_t db2 = (uint32_t)(b >> 32);
            const uint32_t n1 = __reduce_min_sync(0xffffffffu, db2);
            const uint32_t c2 = (db2 == n1) ? (uint32_t)b : 0xffffffffu;
            const uint32_t n2 = __reduce_min_sync(0xffffffffu, c2);
            if (lane == 0)
                s_minkey[row] = ((unsigned long long)n1 << 32) |
                                ((unsigned long long)row << 9) | (n2 & 0x1ffu);
        }
        __syncthreads();                               // barrier 3
    }
}

// ---------------------------------------------------------------------------
// Kernel 4: gather + average -> out[b][t][hw]
// ---------------------------------------------------------------------------
__global__ __launch_bounds__(256) void gather_kernel(const float* __restrict__ x,
                                                     float* __restrict__ out) {
    const int t = blockIdx.x;
    const int b = blockIdx.y;
    const int v1 = g_v1[t];
    const int v2 = g_v2[t];
    const float4* p1 = (const float4*)(x + ((size_t)b * C + v1) * HW);
    const float4* p2 = (const float4*)(x + ((size_t)b * C + v2) * HW);
    float4* po = (float4*)(out + ((size_t)b * T_STEPS + t) * HW);
    for (int q = threadIdx.x; q < HW / 4; q += blockDim.x) {
        const float4 a = p1[q];
        const float4 c = p2[q];
        float4 r;
        r.x = 0.5f * (a.x + c.x);
        r.y = 0.5f * (a.y + c.y);
        r.z = 0.5f * (a.z + c.z);
        r.w = 0.5f * (a.w + c.w);
        po[q] = r;
    }
}

// ---------------------------------------------------------------------------
extern "C" void kernel_launch(void* const* d_in, const int* in_sizes, int n_in,
                              void* d_out, int out_size) {
    const float* x = (const float*)d_in[0];
    float* out = (float*)d_out;

    static bool attr_set = false;
    if (!attr_set) {
        cudaFuncSetAttribute(select_kernel,
                             cudaFuncAttributeMaxDynamicSharedMemorySize,
                             SMEM_D2_BYTES);
        cudaFuncSetAttribute(gram_kernel,
                             cudaFuncAttributeMaxDynamicSharedMemorySize,
                             GRAM_SMEM_BYTES);
        attr_set = true;
    }

    convert_kernel<<<BATCH * C, 256>>>(x);
    gram_kernel<<<dim3(3, NSLICE), 256, GRAM_SMEM_BYTES>>>();
    reduce_kernel<<<144, 256>>>();
    select_kernel<<<148, SEL_THREADS, SMEM_D2_BYTES>>>();
    gather_kernel<<<dim3(T_STEPS, BATCH), 256>>>(x, out);
}